// round 15
// baseline (speedup 1.0000x reference)
#include <cuda_runtime.h>
#include <cuda_bf16.h>
#include <cstdint>

#define B_      32
#define TENC    512
#define TDEC    32
#define DIM     256
#define VOCAB_  32000
#define SOS_    1
#define NROW    (TDEC * B_)                 // 1024 step-rows, row = t*32 + b
#define NTILE_E 1024                        // enc GEMM tiles (256 m x 4 n)
#define NTILE_H 96                          // hV/uch GEMM tiles (3 gemms x 16 m x 2 n)
#define NTILE_V ((NROW / 64) * (VOCAB_ / 128))   // 16 * 250 = 4000

// ---------------- device scratch ----------------
__device__ float g_encW[B_ * TENC * 512];   // cols 0-255: enc@Wm.T+bm, 256-511: enc@Wc.T+bc
__device__ float g_H[NROW * DIM];           // all hidden states, row = t*32+b
__device__ float g_hVm2[NROW * DIM];
__device__ float g_hVc2[NROW * DIM];
__device__ float g_uch2[NROW * DIM];        // Wcomb_h @ H_t
__device__ float g_p2[NROW * TENC];
__device__ float g_ecb2[NROW * TENC];
__device__ float g_attn[NROW * DIM];        // row = t*32+b
__device__ float g_xw[B_ * (TDEC + 1) * DIM];
__device__ float g_WihT[256 * 256];         // [k][o]
__device__ float g_WhhT[256 * 256];         // [k][o]
__device__ float g_WcombT[512 * 256];       // [k][o], k<256 ctx-half
__device__ float g_Wmc[512 * 256];          // rows: o<256 Wm[o], else Wc[o-256]
__device__ float g_Wch[256 * 256];          // Wcomb h-half, raw rows [o][k]
__device__ float g_bmc[512];
__device__ float g_biasr[256];
__device__ float g_wm[256];
__device__ float g_wc[256];
__device__ float g_cst[2];
__device__ float g_zero[256];
__device__ unsigned g_hcnt[TDEC];           // batches that finished H_t
__device__ unsigned g_scnt[TDEC];           // batches that finished attn(t)
__device__ unsigned g_tile;                 // vocab tile queue

// ---------------- shared memory union ----------------
struct SmSt {
    float alpha[512];
    float h[256];
    float eu[512], ratio[512], beta[512];
    float ctx[256];
    float part[1024];
    float w8[32];
};
struct __align__(16) SmGm {
    unsigned long long Ap[64][10];
    unsigned long long Bp[128][10];
};
union SmU {
    SmSt st;
    SmGm gm;
};

// ---------------- helpers ----------------
__device__ __forceinline__ float warp_sum(float v) {
#pragma unroll
    for (int s = 16; s; s >>= 1) v += __shfl_xor_sync(0xffffffffu, v, s);
    return v;
}
__device__ __forceinline__ float tanh_fast(float x) {
    float e = __expf(2.0f * x);
    return 1.0f - __fdividef(2.0f, e + 1.0f);
}
__device__ __forceinline__ float tanh_hw(float x) {
    float y;
    asm("tanh.approx.f32 %0, %1;" : "=f"(y) : "f"(x));
    return y;
}
__device__ __forceinline__ float sigmoid_fast(float x) {
    return __fdividef(1.0f, 1.0f + __expf(-x));
}
__device__ __forceinline__ unsigned long long pk2(float lo, float hi) {
    unsigned long long r;
    asm("mov.b64 %0, {%1, %2};" : "=l"(r) : "f"(lo), "f"(hi));
    return r;
}
__device__ __forceinline__ void fma2(unsigned long long& acc, unsigned long long a,
                                     unsigned long long b) {
    asm("fma.rn.f32x2 %0, %1, %2, %0;" : "+l"(acc) : "l"(a), "l"(b));
}
__device__ __forceinline__ void unpack2(unsigned long long v, float& lo, float& hi) {
    asm("mov.b64 {%0, %1}, %2;" : "=f"(lo), "=f"(hi) : "l"(v));
}

__device__ __forceinline__ float pair_excl(float ps, float* s_w8) {
    int tid = threadIdx.x, lane = tid & 31, wid = tid >> 5;
    float s = ps;
#pragma unroll
    for (int d = 1; d < 32; d <<= 1) {
        float n = __shfl_up_sync(0xffffffffu, s, d);
        if (lane >= d) s += n;
    }
    __syncthreads();
    if (lane == 31) s_w8[wid] = s;
    __syncthreads();
    if (tid < 32) {
        float v = (lane < 8) ? s_w8[lane] : 0.0f;
#pragma unroll
        for (int d = 1; d < 8; d <<= 1) {
            float n = __shfl_up_sync(0xffffffffu, v, d);
            if (lane >= d) v += n;
        }
        if (lane < 8) s_w8[lane] = v;
    }
    __syncthreads();
    float woff = wid ? s_w8[wid - 1] : 0.0f;
    return woff + (s - ps);
}

__device__ __forceinline__ float max512(float m, float* s_w8) {
    int tid = threadIdx.x, lane = tid & 31, wid = tid >> 5;
#pragma unroll
    for (int s = 16; s; s >>= 1) m = fmaxf(m, __shfl_xor_sync(0xffffffffu, m, s));
    __syncthreads();
    if (lane == 0) s_w8[wid] = m;
    __syncthreads();
    if (tid < 32) {
        float v = (lane < 8) ? s_w8[lane] : -1e30f;
#pragma unroll
        for (int s = 4; s; s >>= 1) v = fmaxf(v, __shfl_xor_sync(0xffffffffu, v, s));
        if (lane == 0) s_w8[0] = v;
    }
    __syncthreads();
    return s_w8[0];
}

__device__ __forceinline__ float gemv256(const float* __restrict__ WT,
                                         const float* __restrict__ x, float* s_part) {
    int tid = threadIdx.x;
    int j = tid & 63, kq = tid >> 6;
    __syncthreads();
    const float4* Wp = reinterpret_cast<const float4*>(WT);
    float4 acc = make_float4(0.f, 0.f, 0.f, 0.f);
    int k0 = kq * 64;
#pragma unroll 8
    for (int k = k0; k < k0 + 64; ++k) {
        float f = x[k];
        float4 w = Wp[(size_t)k * 64 + j];
        acc.x = fmaf(f, w.x, acc.x);
        acc.y = fmaf(f, w.y, acc.y);
        acc.z = fmaf(f, w.z, acc.z);
        acc.w = fmaf(f, w.w, acc.w);
    }
    reinterpret_cast<float4*>(s_part)[kq * 64 + j] = acc;
    __syncthreads();
    return s_part[tid] + s_part[256 + tid] + s_part[512 + tid] + s_part[768 + tid];
}

__device__ __forceinline__ void spin_cta_multi(unsigned* base, int i0, int n, unsigned v) {
    if (threadIdx.x < (unsigned)n) {
        const volatile unsigned* f = (const volatile unsigned*)(base + i0 + threadIdx.x);
        while (*f < v) {}
    }
    __syncthreads();
}

// ---------------- GEMM tile: C[64,128] = A[64x256] @ B[128x256]^T + bias --------
template <bool REMAP, bool ACG>
__device__ void gemm_tile64(const float* __restrict__ A, const float* __restrict__ Bw,
                            const float* __restrict__ bias, float* __restrict__ C, int bm,
                            int bn, int N, SmGm* sg) {
    const int K = 256;
    int tid = threadIdx.x, tx = tid & 15, ty = tid >> 4;
    int lrowA = tid >> 2, kbA = (tid & 3) * 2;
    int lrowB = tid >> 1, kbB = (tid & 1) * 4;
    const float* Aptr = A + (size_t)(bm + lrowA) * K + (tid & 3) * 4;
    const float* Bptr = Bw + (size_t)(bn + lrowB) * K + (tid & 1) * 8;

    unsigned long long acc[4][8];
#pragma unroll
    for (int r = 0; r < 4; ++r)
#pragma unroll
        for (int c = 0; c < 8; ++c) acc[r][c] = 0ull;

    float4 fa, fb0, fb1;
    fa = ACG ? __ldcg((const float4*)Aptr) : *(const float4*)Aptr;
    fb0 = *(const float4*)Bptr;
    fb1 = *(const float4*)(Bptr + 4);

#pragma unroll 1
    for (int k0 = 0; k0 < K; k0 += 16) {
        sg->Ap[lrowA][kbA + 0] = pk2(fa.x, fa.y);
        sg->Ap[lrowA][kbA + 1] = pk2(fa.z, fa.w);
        sg->Bp[lrowB][kbB + 0] = pk2(fb0.x, fb0.y);
        sg->Bp[lrowB][kbB + 1] = pk2(fb0.z, fb0.w);
        sg->Bp[lrowB][kbB + 2] = pk2(fb1.x, fb1.y);
        sg->Bp[lrowB][kbB + 3] = pk2(fb1.z, fb1.w);
        __syncthreads();
        if (k0 + 16 < K) {
            fa = ACG ? __ldcg((const float4*)(Aptr + k0 + 16))
                     : *(const float4*)(Aptr + k0 + 16);
            fb0 = *(const float4*)(Bptr + k0 + 16);
            fb1 = *(const float4*)(Bptr + k0 + 20);
        }
#pragma unroll
        for (int u = 0; u < 4; ++u) {
            ulonglong2 a2[4], b2[8];
#pragma unroll
            for (int r = 0; r < 4; ++r)
                a2[r] = *reinterpret_cast<const ulonglong2*>(&sg->Ap[ty + 16 * r][2 * u]);
#pragma unroll
            for (int c = 0; c < 8; ++c)
                b2[c] = *reinterpret_cast<const ulonglong2*>(&sg->Bp[tx + 16 * c][2 * u]);
#pragma unroll
            for (int r = 0; r < 4; ++r)
#pragma unroll
                for (int c = 0; c < 8; ++c) {
                    fma2(acc[r][c], a2[r].x, b2[c].x);
                    fma2(acc[r][c], a2[r].y, b2[c].y);
                }
        }
        __syncthreads();
    }

    float bb[8];
#pragma unroll
    for (int c = 0; c < 8; ++c) bb[c] = __ldg(&bias[bn + tx + 16 * c]);
#pragma unroll
    for (int r = 0; r < 4; ++r) {
        int row = bm + ty + 16 * r;
        float* crow;
        if (REMAP) {
            crow = C + (size_t)((row & 31) * TDEC + (row >> 5)) * N;
        } else {
            crow = C + (size_t)row * N;
        }
#pragma unroll
        for (int c = 0; c < 8; ++c) {
            float lo, hi;
            unpack2(acc[r][c], lo, hi);
            crow[bn + tx + 16 * c] = lo + hi + bb[c];
        }
    }
}

// ---------------- init ----------------
__global__ void k_init(const float* __restrict__ W_ih, const float* __restrict__ b_ih,
                       const float* __restrict__ W_hh, const float* __restrict__ b_hh,
                       const float* __restrict__ W_comb, const float* __restrict__ Wm,
                       const float* __restrict__ Wc, const float* __restrict__ bm,
                       const float* __restrict__ bc, const float* __restrict__ vvm,
                       const float* __restrict__ gm, const float* __restrict__ vbm,
                       const float* __restrict__ rm, const float* __restrict__ vvc,
                       const float* __restrict__ gc, const float* __restrict__ vbc,
                       const float* __restrict__ rc) {
    int bidx = blockIdx.x, tid = threadIdx.x;
    if (bidx < 96) {
        for (int idx = bidx * 256 + tid; idx < 458752; idx += 96 * 256) {
            if (idx < 65536) {
                int k = idx >> 8, o = idx & 255;
                g_WihT[idx] = W_ih[o * 256 + k];
            } else if (idx < 131072) {
                int r = idx - 65536;
                int k = r >> 8, o = r & 255;
                g_WhhT[r] = W_hh[o * 256 + k];
            } else if (idx < 262144) {
                int r = idx - 131072;
                int k = r >> 8, o = r & 255;
                g_WcombT[r] = W_comb[o * 512 + k];
            } else if (idx < 393216) {
                int r = idx - 262144;
                int o = r >> 8, k = r & 255;
                g_Wmc[r] = (o < 256) ? Wm[o * 256 + k] : Wc[(o - 256) * 256 + k];
            } else {
                int r = idx - 393216;      // Wch: raw rows, h-half of W_comb
                int o = r >> 8, k = r & 255;
                g_Wch[r] = W_comb[o * 512 + 256 + k];
            }
        }
    } else {
        __shared__ float red[256];
        if (tid < TDEC) {
            g_hcnt[tid] = 0u;
            g_scnt[tid] = 0u;
        }
        if (tid == 0) g_tile = 0u;
        g_zero[tid] = 0.0f;
        g_bmc[tid] = bm[tid];
        g_bmc[256 + tid] = bc[tid];
        float v = vvm[tid];
        red[tid] = v * v;
        __syncthreads();
        for (int s = 128; s > 0; s >>= 1) {
            if (tid < s) red[tid] += red[tid + s];
            __syncthreads();
        }
        float nm = sqrtf(red[0]);
        __syncthreads();
        g_wm[tid] = vvm[tid] * gm[0] / nm;
        float v2 = vvc[tid];
        red[tid] = v2 * v2;
        __syncthreads();
        for (int s = 128; s > 0; s >>= 1) {
            if (tid < s) red[tid] += red[tid + s];
            __syncthreads();
        }
        float nc = sqrtf(red[0]);
        __syncthreads();
        g_wc[tid] = vvc[tid] * gc[0] / nc;
        g_biasr[tid] = b_ih[tid] + b_hh[tid];
        if (tid == 0) {
            g_cst[0] = vbm[0] + rm[0];
            g_cst[1] = vbc[0] + rc[0];
        }
    }
}

// ---------------- token projections ----------------
__global__ __launch_bounds__(256) void k_xw(const int* __restrict__ dec,
                                            const float* __restrict__ emb) {
    __shared__ float s_x[256];
    __shared__ float s_part[1024];
    int t = blockIdx.x, b = blockIdx.y, tid = threadIdx.x;
    int tok = (t == 0) ? SOS_ : dec[b * TDEC + (t - 1)];
    s_x[tid] = __ldg(&emb[(size_t)tok * DIM + tid]);
    float y = gemv256(g_WihT, s_x, s_part) + g_biasr[tid];
    g_xw[((size_t)b * (TDEC + 1) + t) * DIM + tid] = y;
}

// ---------------- k1: H chain (32 CTAs) + enc GEMM + hV/uch GEMMs (116 workers) ------
__global__ __launch_bounds__(256) void k_phase1(const float* __restrict__ enc,
                                                const float* __restrict__ h0,
                                                const float* __restrict__ Vm,
                                                const float* __restrict__ Vc) {
    __shared__ SmU su;
    int tid = threadIdx.x, cta = blockIdx.x;

    if (cta < 32) {
        // pure H chain for batch b: zero cross-CTA waits
        int b = cta;
        su.st.h[tid] = h0[b * DIM + tid];
#pragma unroll 1
        for (int t = 0; t < TDEC; ++t) {
            float yh = gemv256(g_WhhT, su.st.h, su.st.part);
            float hn =
                tanh_fast(yh + __ldg(&g_xw[((size_t)b * (TDEC + 1) + t) * DIM + tid]));
            __syncthreads();
            su.st.h[tid] = hn;
            __stcg(&g_H[((size_t)t * B_ + b) * DIM + tid], hn);
            __threadfence();
            __syncthreads();
            if (tid == 0) atomicAdd(&g_hcnt[t], 1u);
        }
    } else {
        int w = cta - 32;
        // encoder projection: [16384,256] @ [512,256]^T, no gating
        for (int idx = w; idx < NTILE_E; idx += 116) {
            gemm_tile64<false, false>(enc, g_Wmc, g_bmc, g_encW, (idx >> 2) * 64,
                                      (idx & 3) * 128, 512, &su.gm);
        }
        // hV / uch projections: gated on H completion for covered t-pair
        for (int idx = w; idx < NTILE_H; idx += 116) {
            int g2 = idx / 32, r = idx - g2 * 32;
            int m = r >> 1, n = r & 1;
            spin_cta_multi(g_hcnt, 2 * m, 2, 32u);
            __threadfence();
            const float* Bw = (g2 == 0) ? Vm : (g2 == 1) ? Vc : g_Wch;
            float* C = (g2 == 0) ? g_hVm2 : (g2 == 1) ? g_hVc2 : g_uch2;
            gemm_tile64<false, true>(g_H, Bw, g_zero, C, m * 64, n * 128, 256, &su.gm);
        }
    }
}

// ---------------- k2: bulk energy, all 1024 (b,t) units, full chip ----------------
__global__ __launch_bounds__(256) void k_energy(const float* __restrict__ noise) {
    int tid = threadIdx.x, wid = tid >> 5, lane = tid & 31;
    int a0 = lane * 8;
    float cm = g_cst[0], cc = g_cst[1];
    float rwm[8], rwc[8];
#pragma unroll
    for (int j = 0; j < 8; ++j) {
        rwm[j] = __ldg(&g_wm[a0 + j]);
        rwc[j] = __ldg(&g_wc[a0 + j]);
    }
#pragma unroll 1
    for (int u = blockIdx.x; u < NROW; u += 148) {
        int t = u >> 5, b = u & 31;
        float rhm[8], rhc[8];
        {
            const float* hm = g_hVm2 + (size_t)u * DIM + a0;
            const float* hc = g_hVc2 + (size_t)u * DIM + a0;
            float4 v0 = *(const float4*)hm, v1 = *(const float4*)(hm + 4);
            rhm[0] = v0.x; rhm[1] = v0.y; rhm[2] = v0.z; rhm[3] = v0.w;
            rhm[4] = v1.x; rhm[5] = v1.y; rhm[6] = v1.z; rhm[7] = v1.w;
            float4 w0 = *(const float4*)hc, w1 = *(const float4*)(hc + 4);
            rhc[0] = w0.x; rhc[1] = w0.y; rhc[2] = w0.z; rhc[3] = w0.w;
            rhc[4] = w1.x; rhc[5] = w1.y; rhc[6] = w1.z; rhc[7] = w1.w;
        }
        float* out_p = g_p2 + (size_t)u * TENC;
        float* out_ec = g_ecb2 + (size_t)u * TENC;
        const size_t base = (size_t)b * TENC;
#pragma unroll 1
        for (int tt = wid; tt < TENC; tt += 8) {
            const float4* row4 =
                reinterpret_cast<const float4*>(g_encW + (base + tt) * 512);
            float4 m0 = __ldcg(row4 + lane * 2), m1 = __ldcg(row4 + lane * 2 + 1);
            float4 c0 = __ldcg(row4 + 64 + lane * 2), c1 = __ldcg(row4 + 64 + lane * 2 + 1);
            float mv[8] = {m0.x, m0.y, m0.z, m0.w, m1.x, m1.y, m1.z, m1.w};
            float cv[8] = {c0.x, c0.y, c0.z, c0.w, c1.x, c1.y, c1.z, c1.w};
            float am = 0.f, ac = 0.f;
#pragma unroll
            for (int j = 0; j < 8; ++j) {
                am = fmaf(tanh_hw(mv[j] + rhm[j]), rwm[j], am);
                ac = fmaf(tanh_hw(cv[j] + rhc[j]), rwc[j], ac);
            }
            am = warp_sum(am);
            ac = warp_sum(ac);
            if (lane == 0) {
                float pp = sigmoid_fast(
                    am + cm + __ldg(&noise[((size_t)t * B_ + b) * TENC + tt]));
                __stcg(&out_p[tt], pp);
                __stcg(&out_ec[tt], ac + cc);
            }
        }
    }
}

// ---------------- k3: post chains (32 CTAs, wait-free) + gated vocab GEMM ------------
__global__ __launch_bounds__(256) void k_post(const float* __restrict__ enc,
                                              const float* __restrict__ Wproj,
                                              const float* __restrict__ bproj,
                                              float* __restrict__ out) {
    __shared__ SmU su;
    __shared__ int s_idx;
    int tid = threadIdx.x, cta = blockIdx.x;

    if (cta < 32) {
        int b = cta;
        su.st.alpha[tid] = (tid == 0) ? 1.0f : 0.0f;
        su.st.alpha[256 + tid] = 0.0f;
        __syncthreads();
#pragma unroll 1
        for (int t = 0; t < TDEC; ++t) {
            size_t row = (size_t)t * B_ + b;
            int j0 = 2 * tid, j1 = 2 * tid + 1;
            float p0 = __ldcg(&g_p2[row * TENC + j0]);
            float p1 = __ldcg(&g_p2[row * TENC + j1]);
            float l0 = __logf(fminf(fmaxf(1.0f - p0, 1e-10f), 1.0f));
            float l1 = __logf(fminf(fmaxf(1.0f - p1, 1e-10f), 1.0f));
            float eP = pair_excl(l0 + l1, su.st.w8);
            float cp0 = __expf(eP);
            float cp1 = __expf(eP + l0);
            float A0 = su.st.alpha[j0], A1 = su.st.alpha[j1];
            float r0 = __fdividef(A0, fmaxf(cp0, 1e-10f));
            float r1 = __fdividef(A1, fmaxf(cp1, 1e-10f));
            float eS = pair_excl(r0 + r1, su.st.w8);
            float na0 = p0 * cp0 * (eS + r0);
            float na1 = p1 * cp1 * (eS + r0 + r1);
            su.st.alpha[j0] = na0;
            su.st.alpha[j1] = na1;

            float e0 = __ldcg(&g_ecb2[row * TENC + j0]);
            float e1 = __ldcg(&g_ecb2[row * TENC + j1]);
            float mx = max512(fmaxf(e0, e1), su.st.w8);
            float eu0 = __expf(e0 - mx), eu1 = __expf(e1 - mx);
            su.st.eu[j0] = eu0;
            su.st.eu[j1] = eu1;
            __syncthreads();
            float d0 = 0.0f, d1 = 0.0f;
#pragma unroll
            for (int k = 0; k < 8; ++k) {
                int q0i = j0 - k, q1i = j1 - k;
                if (q0i >= 0) d0 += su.st.eu[q0i];
                if (q1i >= 0) d1 += su.st.eu[q1i];
            }
            su.st.ratio[j0] = __fdividef(na0, fmaxf(d0, 1e-10f));
            su.st.ratio[j1] = __fdividef(na1, fmaxf(d1, 1e-10f));
            __syncthreads();
            float b0 = 0.0f, b1 = 0.0f;
#pragma unroll
            for (int k = 0; k < 8; ++k) {
                int q0i = j0 + k, q1i = j1 + k;
                if (q0i < TENC) b0 += su.st.ratio[q0i];
                if (q1i < TENC) b1 += su.st.ratio[q1i];
            }
            su.st.beta[j0] = eu0 * b0;
            su.st.beta[j1] = eu1 * b1;
            __syncthreads();

            // context = beta @ enc[b]
            {
                int jj = tid & 63, tq4 = tid >> 6;
                const float4* ep = reinterpret_cast<const float4*>(enc) +
                                   (size_t)(b * TENC + tq4 * 128) * (DIM / 4) + jj;
                float4 acc = make_float4(0.f, 0.f, 0.f, 0.f);
#pragma unroll 4
                for (int ttt = 0; ttt < 128; ++ttt) {
                    float f = su.st.beta[tq4 * 128 + ttt];
                    float4 e4 = ep[(size_t)ttt * 64];
                    acc.x = fmaf(f, e4.x, acc.x);
                    acc.y = fmaf(f, e4.y, acc.y);
                    acc.z = fmaf(f, e4.z, acc.z);
                    acc.w = fmaf(f, e4.w, acc.w);
                }
                reinterpret_cast<float4*>(su.st.part)[tq4 * 64 + jj] = acc;
            }
            __syncthreads();
            su.st.ctx[tid] = su.st.part[tid] + su.st.part[256 + tid] +
                             su.st.part[512 + tid] + su.st.part[768 + tid];

            // attn = tanh(Wcomb_ctx@ctx + uch) — uch precomputed, no wait
            float av = gemv256(g_WcombT, su.st.ctx, su.st.part);
            float at = tanh_fast(av + __ldg(&g_uch2[row * DIM + tid]));
            __stcg(&g_attn[row * DIM + tid], at);
            __threadfence();
            __syncthreads();
            if (tid == 0) atomicAdd(&g_scnt[t], 1u);
        }
    }

    // everyone drains the vocab queue (tiles gated on step completion)
    for (;;) {
        __syncthreads();
        if (tid == 0) s_idx = (int)atomicAdd(&g_tile, 1u);
        __syncthreads();
        int idx = s_idx;
        if (idx >= NTILE_V) break;
        int m = idx / (VOCAB_ / 128);
        int n = idx - m * (VOCAB_ / 128);
        if (tid == 0) {
            const volatile unsigned* f = &g_scnt[2 * m + 1];
            while (*f < 32u) __nanosleep(256);
        }
        __syncthreads();
        __threadfence();
        gemm_tile64<true, true>(g_attn, Wproj, bproj, out, m * 64, n * 128, VOCAB_,
                                &su.gm);
    }
}

// ---------------- launch ----------------
extern "C" void kernel_launch(void* const* d_in, const int* in_sizes, int n_in, void* d_out,
                              int out_size) {
    (void)in_sizes;
    (void)n_in;
    (void)out_size;
    const float* enc = (const float*)d_in[0];
    const int* dec = (const int*)d_in[1];
    const float* h0 = (const float*)d_in[2];
    const float* noise = (const float*)d_in[3];
    const float* emb = (const float*)d_in[4];
    const float* W_ih = (const float*)d_in[5];
    const float* b_ih = (const float*)d_in[6];
    const float* W_hh = (const float*)d_in[7];
    const float* b_hh = (const float*)d_in[8];
    const float* Wm = (const float*)d_in[9];
    const float* Vm = (const float*)d_in[10];
    const float* bm = (const float*)d_in[11];
    const float* vvm = (const float*)d_in[12];
    const float* gm = (const float*)d_in[13];
    const float* vbm = (const float*)d_in[14];
    const float* rm = (const float*)d_in[15];
    const float* Wc = (const float*)d_in[16];
    const float* Vc = (const float*)d_in[17];
    const float* bc = (const float*)d_in[18];
    const float* vvc = (const float*)d_in[19];
    const float* gc = (const float*)d_in[20];
    const float* vbc = (const float*)d_in[21];
    const float* rc = (const float*)d_in[22];
    const float* W_comb = (const float*)d_in[23];
    const float* W_proj = (const float*)d_in[24];
    const float* b_proj = (const float*)d_in[25];
    float* out = (float*)d_out;

    k_init<<<97, 256>>>(W_ih, b_ih, W_hh, b_hh, W_comb, Wm, Wc, bm, bc, vvm, gm, vbm, rm,
                        vvc, gc, vbc, rc);
    k_xw<<<dim3(TDEC + 1, B_), 256>>>(dec, emb);
    k_phase1<<<148, 256>>>(enc, h0, Vm, Vc);
    k_energy<<<148, 256>>>(noise);
    k_post<<<148, 256>>>(enc, W_proj, b_proj, out);
}

// round 16
// speedup vs baseline: 1.3822x; 1.3822x over previous
#include <cuda_runtime.h>
#include <cuda_bf16.h>
#include <cstdint>

#define B_      32
#define TENC    512
#define TDEC    32
#define DIM     256
#define VOCAB_  32000
#define SOS_    1
#define NROW    (TDEC * B_)                 // 1024 step-rows, row = t*32 + b
#define NTILE_E 1024                        // enc GEMM tiles (256 m x 4 n)
#define NTILE_H 96                          // hV/uch GEMM tiles (3 gemms x 16 m x 2 n)
#define NTILE_V ((NROW / 64) * (VOCAB_ / 128))   // 16 * 250 = 4000

// ---------------- device scratch ----------------
__device__ float g_encW[B_ * TENC * 512];   // cols 0-255: enc@Wm.T+bm, 256-511: enc@Wc.T+bc
__device__ float g_H[NROW * DIM];           // all hidden states, row = t*32+b
__device__ float g_hVm2[NROW * DIM];
__device__ float g_hVc2[NROW * DIM];
__device__ float g_uch2[NROW * DIM];        // Wcomb_h @ H_t
__device__ float g_p2[NROW * TENC];
__device__ float g_ecb2[NROW * TENC];
__device__ float g_attn[NROW * DIM];        // row = t*32+b
__device__ float g_xw[B_ * (TDEC + 1) * DIM];
__device__ float g_WihT[256 * 256];         // [k][o]
__device__ float g_WhhT[256 * 256];         // [k][o]
__device__ float g_WcombT[512 * 256];       // [k][o], k<256 ctx-half
__device__ float g_Wmc[512 * 256];          // rows: o<256 Wm[o], else Wc[o-256]
__device__ float g_Wch[256 * 256];          // Wcomb h-half, raw rows [o][k]
__device__ float g_bmc[512];
__device__ float g_biasr[256];
__device__ float g_wm[256];
__device__ float g_wc[256];
__device__ float g_cst[2];
__device__ float g_zero[256];
__device__ unsigned g_hcnt[TDEC];           // batches that finished H_t
__device__ unsigned g_scnt[TDEC];           // batches that finished attn(t)
__device__ unsigned g_tile;                 // vocab tile queue

// ---------------- shared memory union ----------------
struct SmSt {
    float alpha[512];
    float h[256];
    float eu[512], ratio[512], beta[512];
    float ctx[256];
    float part[1024];
    float w8[32];
};
struct __align__(16) SmGm {
    unsigned long long Ap[64][10];
    unsigned long long Bp[128][10];
};
union SmU {
    SmSt st;
    SmGm gm;
};

// ---------------- helpers ----------------
__device__ __forceinline__ float warp_sum(float v) {
#pragma unroll
    for (int s = 16; s; s >>= 1) v += __shfl_xor_sync(0xffffffffu, v, s);
    return v;
}
__device__ __forceinline__ float tanh_fast(float x) {
    float e = __expf(2.0f * x);
    return 1.0f - __fdividef(2.0f, e + 1.0f);
}
__device__ __forceinline__ float tanh_hw(float x) {
    float y;
    asm("tanh.approx.f32 %0, %1;" : "=f"(y) : "f"(x));
    return y;
}
__device__ __forceinline__ float sigmoid_fast(float x) {
    return __fdividef(1.0f, 1.0f + __expf(-x));
}
__device__ __forceinline__ unsigned long long pk2(float lo, float hi) {
    unsigned long long r;
    asm("mov.b64 %0, {%1, %2};" : "=l"(r) : "f"(lo), "f"(hi));
    return r;
}
__device__ __forceinline__ void fma2(unsigned long long& acc, unsigned long long a,
                                     unsigned long long b) {
    asm("fma.rn.f32x2 %0, %1, %2, %0;" : "+l"(acc) : "l"(a), "l"(b));
}
__device__ __forceinline__ void unpack2(unsigned long long v, float& lo, float& hi) {
    asm("mov.b64 {%0, %1}, %2;" : "=f"(lo), "=f"(hi) : "l"(v));
}

__device__ __forceinline__ float pair_excl(float ps, float* s_w8) {
    int tid = threadIdx.x, lane = tid & 31, wid = tid >> 5;
    float s = ps;
#pragma unroll
    for (int d = 1; d < 32; d <<= 1) {
        float n = __shfl_up_sync(0xffffffffu, s, d);
        if (lane >= d) s += n;
    }
    __syncthreads();
    if (lane == 31) s_w8[wid] = s;
    __syncthreads();
    if (tid < 32) {
        float v = (lane < 8) ? s_w8[lane] : 0.0f;
#pragma unroll
        for (int d = 1; d < 8; d <<= 1) {
            float n = __shfl_up_sync(0xffffffffu, v, d);
            if (lane >= d) v += n;
        }
        if (lane < 8) s_w8[lane] = v;
    }
    __syncthreads();
    float woff = wid ? s_w8[wid - 1] : 0.0f;
    return woff + (s - ps);
}

__device__ __forceinline__ float max512(float m, float* s_w8) {
    int tid = threadIdx.x, lane = tid & 31, wid = tid >> 5;
#pragma unroll
    for (int s = 16; s; s >>= 1) m = fmaxf(m, __shfl_xor_sync(0xffffffffu, m, s));
    __syncthreads();
    if (lane == 0) s_w8[wid] = m;
    __syncthreads();
    if (tid < 32) {
        float v = (lane < 8) ? s_w8[lane] : -1e30f;
#pragma unroll
        for (int s = 4; s; s >>= 1) v = fmaxf(v, __shfl_xor_sync(0xffffffffu, v, s));
        if (lane == 0) s_w8[0] = v;
    }
    __syncthreads();
    return s_w8[0];
}

__device__ __forceinline__ float gemv256(const float* __restrict__ WT,
                                         const float* __restrict__ x, float* s_part) {
    int tid = threadIdx.x;
    int j = tid & 63, kq = tid >> 6;
    __syncthreads();
    const float4* Wp = reinterpret_cast<const float4*>(WT);
    float4 acc = make_float4(0.f, 0.f, 0.f, 0.f);
    int k0 = kq * 64;
#pragma unroll 8
    for (int k = k0; k < k0 + 64; ++k) {
        float f = x[k];
        float4 w = Wp[(size_t)k * 64 + j];
        acc.x = fmaf(f, w.x, acc.x);
        acc.y = fmaf(f, w.y, acc.y);
        acc.z = fmaf(f, w.z, acc.z);
        acc.w = fmaf(f, w.w, acc.w);
    }
    reinterpret_cast<float4*>(s_part)[kq * 64 + j] = acc;
    __syncthreads();
    return s_part[tid] + s_part[256 + tid] + s_part[512 + tid] + s_part[768 + tid];
}

__device__ __forceinline__ void spin_cta_multi(unsigned* base, int i0, int n, unsigned v) {
    if (threadIdx.x < (unsigned)n) {
        const volatile unsigned* f = (const volatile unsigned*)(base + i0 + threadIdx.x);
        while (*f < v) {}
    }
    __syncthreads();
}

// ---------------- GEMM tile: C[64,128] = A[64x256] @ B[128x256]^T + bias --------
template <bool REMAP, bool ACG>
__device__ void gemm_tile64(const float* __restrict__ A, const float* __restrict__ Bw,
                            const float* __restrict__ bias, float* __restrict__ C, int bm,
                            int bn, int N, SmGm* sg) {
    const int K = 256;
    int tid = threadIdx.x, tx = tid & 15, ty = tid >> 4;
    int lrowA = tid >> 2, kbA = (tid & 3) * 2;
    int lrowB = tid >> 1, kbB = (tid & 1) * 4;
    const float* Aptr = A + (size_t)(bm + lrowA) * K + (tid & 3) * 4;
    const float* Bptr = Bw + (size_t)(bn + lrowB) * K + (tid & 1) * 8;

    unsigned long long acc[4][8];
#pragma unroll
    for (int r = 0; r < 4; ++r)
#pragma unroll
        for (int c = 0; c < 8; ++c) acc[r][c] = 0ull;

    float4 fa, fb0, fb1;
    fa = ACG ? __ldcg((const float4*)Aptr) : *(const float4*)Aptr;
    fb0 = *(const float4*)Bptr;
    fb1 = *(const float4*)(Bptr + 4);

#pragma unroll 1
    for (int k0 = 0; k0 < K; k0 += 16) {
        sg->Ap[lrowA][kbA + 0] = pk2(fa.x, fa.y);
        sg->Ap[lrowA][kbA + 1] = pk2(fa.z, fa.w);
        sg->Bp[lrowB][kbB + 0] = pk2(fb0.x, fb0.y);
        sg->Bp[lrowB][kbB + 1] = pk2(fb0.z, fb0.w);
        sg->Bp[lrowB][kbB + 2] = pk2(fb1.x, fb1.y);
        sg->Bp[lrowB][kbB + 3] = pk2(fb1.z, fb1.w);
        __syncthreads();
        if (k0 + 16 < K) {
            fa = ACG ? __ldcg((const float4*)(Aptr + k0 + 16))
                     : *(const float4*)(Aptr + k0 + 16);
            fb0 = *(const float4*)(Bptr + k0 + 16);
            fb1 = *(const float4*)(Bptr + k0 + 20);
        }
#pragma unroll
        for (int u = 0; u < 4; ++u) {
            ulonglong2 a2[4], b2[8];
#pragma unroll
            for (int r = 0; r < 4; ++r)
                a2[r] = *reinterpret_cast<const ulonglong2*>(&sg->Ap[ty + 16 * r][2 * u]);
#pragma unroll
            for (int c = 0; c < 8; ++c)
                b2[c] = *reinterpret_cast<const ulonglong2*>(&sg->Bp[tx + 16 * c][2 * u]);
#pragma unroll
            for (int r = 0; r < 4; ++r)
#pragma unroll
                for (int c = 0; c < 8; ++c) {
                    fma2(acc[r][c], a2[r].x, b2[c].x);
                    fma2(acc[r][c], a2[r].y, b2[c].y);
                }
        }
        __syncthreads();
    }

    float bb[8];
#pragma unroll
    for (int c = 0; c < 8; ++c) bb[c] = __ldg(&bias[bn + tx + 16 * c]);
#pragma unroll
    for (int r = 0; r < 4; ++r) {
        int row = bm + ty + 16 * r;
        float* crow;
        if (REMAP) {
            crow = C + (size_t)((row & 31) * TDEC + (row >> 5)) * N;
        } else {
            crow = C + (size_t)row * N;
        }
#pragma unroll
        for (int c = 0; c < 8; ++c) {
            float lo, hi;
            unpack2(acc[r][c], lo, hi);
            crow[bn + tx + 16 * c] = lo + hi + bb[c];
        }
    }
}

// ---------------- init ----------------
__global__ void k_init(const float* __restrict__ W_ih, const float* __restrict__ b_ih,
                       const float* __restrict__ W_hh, const float* __restrict__ b_hh,
                       const float* __restrict__ W_comb, const float* __restrict__ Wm,
                       const float* __restrict__ Wc, const float* __restrict__ bm,
                       const float* __restrict__ bc, const float* __restrict__ vvm,
                       const float* __restrict__ gm, const float* __restrict__ vbm,
                       const float* __restrict__ rm, const float* __restrict__ vvc,
                       const float* __restrict__ gc, const float* __restrict__ vbc,
                       const float* __restrict__ rc) {
    int bidx = blockIdx.x, tid = threadIdx.x;
    if (bidx < 96) {
        for (int idx = bidx * 256 + tid; idx < 458752; idx += 96 * 256) {
            if (idx < 65536) {
                int k = idx >> 8, o = idx & 255;
                g_WihT[idx] = W_ih[o * 256 + k];
            } else if (idx < 131072) {
                int r = idx - 65536;
                int k = r >> 8, o = r & 255;
                g_WhhT[r] = W_hh[o * 256 + k];
            } else if (idx < 262144) {
                int r = idx - 131072;
                int k = r >> 8, o = r & 255;
                g_WcombT[r] = W_comb[o * 512 + k];
            } else if (idx < 393216) {
                int r = idx - 262144;
                int o = r >> 8, k = r & 255;
                g_Wmc[r] = (o < 256) ? Wm[o * 256 + k] : Wc[(o - 256) * 256 + k];
            } else {
                int r = idx - 393216;      // Wch: raw rows, h-half of W_comb
                int o = r >> 8, k = r & 255;
                g_Wch[r] = W_comb[o * 512 + 256 + k];
            }
        }
    } else {
        __shared__ float red[256];
        if (tid < TDEC) {
            g_hcnt[tid] = 0u;
            g_scnt[tid] = 0u;
        }
        if (tid == 0) g_tile = 0u;
        g_zero[tid] = 0.0f;
        g_bmc[tid] = bm[tid];
        g_bmc[256 + tid] = bc[tid];
        float v = vvm[tid];
        red[tid] = v * v;
        __syncthreads();
        for (int s = 128; s > 0; s >>= 1) {
            if (tid < s) red[tid] += red[tid + s];
            __syncthreads();
        }
        float nm = sqrtf(red[0]);
        __syncthreads();
        g_wm[tid] = vvm[tid] * gm[0] / nm;
        float v2 = vvc[tid];
        red[tid] = v2 * v2;
        __syncthreads();
        for (int s = 128; s > 0; s >>= 1) {
            if (tid < s) red[tid] += red[tid + s];
            __syncthreads();
        }
        float nc = sqrtf(red[0]);
        __syncthreads();
        g_wc[tid] = vvc[tid] * gc[0] / nc;
        g_biasr[tid] = b_ih[tid] + b_hh[tid];
        if (tid == 0) {
            g_cst[0] = vbm[0] + rm[0];
            g_cst[1] = vbc[0] + rc[0];
        }
    }
}

// ---------------- token projections ----------------
__global__ __launch_bounds__(256) void k_xw(const int* __restrict__ dec,
                                            const float* __restrict__ emb) {
    __shared__ float s_x[256];
    __shared__ float s_part[1024];
    int t = blockIdx.x, b = blockIdx.y, tid = threadIdx.x;
    int tok = (t == 0) ? SOS_ : dec[b * TDEC + (t - 1)];
    s_x[tid] = __ldg(&emb[(size_t)tok * DIM + tid]);
    float y = gemv256(g_WihT, s_x, s_part) + g_biasr[tid];
    g_xw[((size_t)b * (TDEC + 1) + t) * DIM + tid] = y;
}

// ---------------- k1: H chain (32 CTAs) + enc GEMM + hV/uch GEMMs (workers) ----------
// grid 296, occ 2: workers co-resident with H-chain CTAs fill idle issue slots.
__global__ __launch_bounds__(256, 2) void k_phase1(const float* __restrict__ enc,
                                                   const float* __restrict__ h0,
                                                   const float* __restrict__ Vm,
                                                   const float* __restrict__ Vc) {
    __shared__ SmU su;
    int tid = threadIdx.x, cta = blockIdx.x;
    int nw = gridDim.x - 32;

    if (cta < 32) {
        // pure H chain for batch b: zero cross-CTA waits
        int b = cta;
        su.st.h[tid] = h0[b * DIM + tid];
#pragma unroll 1
        for (int t = 0; t < TDEC; ++t) {
            float yh = gemv256(g_WhhT, su.st.h, su.st.part);
            float hn =
                tanh_fast(yh + __ldg(&g_xw[((size_t)b * (TDEC + 1) + t) * DIM + tid]));
            __syncthreads();
            su.st.h[tid] = hn;
            __stcg(&g_H[((size_t)t * B_ + b) * DIM + tid], hn);
            __threadfence();
            __syncthreads();
            if (tid == 0) atomicAdd(&g_hcnt[t], 1u);
        }
    } else {
        int w = cta - 32;
        // encoder projection: [16384,256] @ [512,256]^T, no gating
        for (int idx = w; idx < NTILE_E; idx += nw) {
            gemm_tile64<false, false>(enc, g_Wmc, g_bmc, g_encW, (idx >> 2) * 64,
                                      (idx & 3) * 128, 512, &su.gm);
        }
        // hV / uch projections: gated on H completion for covered t-pair
        for (int idx = w; idx < NTILE_H; idx += nw) {
            int g2 = idx / 32, r = idx - g2 * 32;
            int m = r >> 1, n = r & 1;
            spin_cta_multi(g_hcnt, 2 * m, 2, 32u);
            __threadfence();
            const float* Bw = (g2 == 0) ? Vm : (g2 == 1) ? Vc : g_Wch;
            float* C = (g2 == 0) ? g_hVm2 : (g2 == 1) ? g_hVc2 : g_uch2;
            gemm_tile64<false, true>(g_H, Bw, g_zero, C, m * 64, n * 128, 256, &su.gm);
        }
    }
}

// ---------------- k2: bulk energy, all 1024 (b,t) units, occ 3 ----------------
__global__ __launch_bounds__(256, 3) void k_energy(const float* __restrict__ noise) {
    int tid = threadIdx.x, wid = tid >> 5, lane = tid & 31;
    int a0 = lane * 8;
    float cm = g_cst[0], cc = g_cst[1];
    float rwm[8], rwc[8];
#pragma unroll
    for (int j = 0; j < 8; ++j) {
        rwm[j] = __ldg(&g_wm[a0 + j]);
        rwc[j] = __ldg(&g_wc[a0 + j]);
    }
#pragma unroll 1
    for (int u = blockIdx.x; u < NROW; u += gridDim.x) {
        int t = u >> 5, b = u & 31;
        float rhm[8], rhc[8];
        {
            const float* hm = g_hVm2 + (size_t)u * DIM + a0;
            const float* hc = g_hVc2 + (size_t)u * DIM + a0;
            float4 v0 = *(const float4*)hm, v1 = *(const float4*)(hm + 4);
            rhm[0] = v0.x; rhm[1] = v0.y; rhm[2] = v0.z; rhm[3] = v0.w;
            rhm[4] = v1.x; rhm[5] = v1.y; rhm[6] = v1.z; rhm[7] = v1.w;
            float4 w0 = *(const float4*)hc, w1 = *(const float4*)(hc + 4);
            rhc[0] = w0.x; rhc[1] = w0.y; rhc[2] = w0.z; rhc[3] = w0.w;
            rhc[4] = w1.x; rhc[5] = w1.y; rhc[6] = w1.z; rhc[7] = w1.w;
        }
        float* out_p = g_p2 + (size_t)u * TENC;
        float* out_ec = g_ecb2 + (size_t)u * TENC;
        const size_t base = (size_t)b * TENC;
#pragma unroll 1
        for (int tt = wid; tt < TENC; tt += 8) {
            const float4* row4 =
                reinterpret_cast<const float4*>(g_encW + (base + tt) * 512);
            float4 m0 = __ldcg(row4 + lane * 2), m1 = __ldcg(row4 + lane * 2 + 1);
            float4 c0 = __ldcg(row4 + 64 + lane * 2), c1 = __ldcg(row4 + 64 + lane * 2 + 1);
            float mv[8] = {m0.x, m0.y, m0.z, m0.w, m1.x, m1.y, m1.z, m1.w};
            float cv[8] = {c0.x, c0.y, c0.z, c0.w, c1.x, c1.y, c1.z, c1.w};
            float am = 0.f, ac = 0.f;
#pragma unroll
            for (int j = 0; j < 8; ++j) {
                am = fmaf(tanh_hw(mv[j] + rhm[j]), rwm[j], am);
                ac = fmaf(tanh_hw(cv[j] + rhc[j]), rwc[j], ac);
            }
            am = warp_sum(am);
            ac = warp_sum(ac);
            if (lane == 0) {
                float pp = sigmoid_fast(
                    am + cm + __ldg(&noise[((size_t)t * B_ + b) * TENC + tt]));
                __stcg(&out_p[tt], pp);
                __stcg(&out_ec[tt], ac + cc);
            }
        }
    }
}

// ---------------- k3: post chains (32 CTAs, wait-free) + gated vocab GEMM ------------
// grid 296, occ 2: vocab workers co-resident with post chains.
__global__ __launch_bounds__(256, 2) void k_post(const float* __restrict__ enc,
                                                 const float* __restrict__ Wproj,
                                                 const float* __restrict__ bproj,
                                                 float* __restrict__ out) {
    __shared__ SmU su;
    __shared__ int s_idx;
    int tid = threadIdx.x, cta = blockIdx.x;

    if (cta < 32) {
        int b = cta;
        su.st.alpha[tid] = (tid == 0) ? 1.0f : 0.0f;
        su.st.alpha[256 + tid] = 0.0f;
        __syncthreads();
#pragma unroll 1
        for (int t = 0; t < TDEC; ++t) {
            size_t row = (size_t)t * B_ + b;
            int j0 = 2 * tid, j1 = 2 * tid + 1;
            float p0 = __ldcg(&g_p2[row * TENC + j0]);
            float p1 = __ldcg(&g_p2[row * TENC + j1]);
            float l0 = __logf(fminf(fmaxf(1.0f - p0, 1e-10f), 1.0f));
            float l1 = __logf(fminf(fmaxf(1.0f - p1, 1e-10f), 1.0f));
            float eP = pair_excl(l0 + l1, su.st.w8);
            float cp0 = __expf(eP);
            float cp1 = __expf(eP + l0);
            float A0 = su.st.alpha[j0], A1 = su.st.alpha[j1];
            float r0 = __fdividef(A0, fmaxf(cp0, 1e-10f));
            float r1 = __fdividef(A1, fmaxf(cp1, 1e-10f));
            float eS = pair_excl(r0 + r1, su.st.w8);
            float na0 = p0 * cp0 * (eS + r0);
            float na1 = p1 * cp1 * (eS + r0 + r1);
            su.st.alpha[j0] = na0;
            su.st.alpha[j1] = na1;

            float e0 = __ldcg(&g_ecb2[row * TENC + j0]);
            float e1 = __ldcg(&g_ecb2[row * TENC + j1]);
            float mx = max512(fmaxf(e0, e1), su.st.w8);
            float eu0 = __expf(e0 - mx), eu1 = __expf(e1 - mx);
            su.st.eu[j0] = eu0;
            su.st.eu[j1] = eu1;
            __syncthreads();
            float d0 = 0.0f, d1 = 0.0f;
#pragma unroll
            for (int k = 0; k < 8; ++k) {
                int q0i = j0 - k, q1i = j1 - k;
                if (q0i >= 0) d0 += su.st.eu[q0i];
                if (q1i >= 0) d1 += su.st.eu[q1i];
            }
            su.st.ratio[j0] = __fdividef(na0, fmaxf(d0, 1e-10f));
            su.st.ratio[j1] = __fdividef(na1, fmaxf(d1, 1e-10f));
            __syncthreads();
            float b0 = 0.0f, b1 = 0.0f;
#pragma unroll
            for (int k = 0; k < 8; ++k) {
                int q0i = j0 + k, q1i = j1 + k;
                if (q0i < TENC) b0 += su.st.ratio[q0i];
                if (q1i < TENC) b1 += su.st.ratio[q1i];
            }
            su.st.beta[j0] = eu0 * b0;
            su.st.beta[j1] = eu1 * b1;
            __syncthreads();

            // context = beta @ enc[b]
            {
                int jj = tid & 63, tq4 = tid >> 6;
                const float4* ep = reinterpret_cast<const float4*>(enc) +
                                   (size_t)(b * TENC + tq4 * 128) * (DIM / 4) + jj;
                float4 acc = make_float4(0.f, 0.f, 0.f, 0.f);
#pragma unroll 4
                for (int ttt = 0; ttt < 128; ++ttt) {
                    float f = su.st.beta[tq4 * 128 + ttt];
                    float4 e4 = ep[(size_t)ttt * 64];
                    acc.x = fmaf(f, e4.x, acc.x);
                    acc.y = fmaf(f, e4.y, acc.y);
                    acc.z = fmaf(f, e4.z, acc.z);
                    acc.w = fmaf(f, e4.w, acc.w);
                }
                reinterpret_cast<float4*>(su.st.part)[tq4 * 64 + jj] = acc;
            }
            __syncthreads();
            su.st.ctx[tid] = su.st.part[tid] + su.st.part[256 + tid] +
                             su.st.part[512 + tid] + su.st.part[768 + tid];

            // attn = tanh(Wcomb_ctx@ctx + uch) — uch precomputed, no wait
            float av = gemv256(g_WcombT, su.st.ctx, su.st.part);
            float at = tanh_fast(av + __ldg(&g_uch2[row * DIM + tid]));
            __stcg(&g_attn[row * DIM + tid], at);
            __threadfence();
            __syncthreads();
            if (tid == 0) atomicAdd(&g_scnt[t], 1u);
        }
    }

    // everyone drains the vocab queue (tiles gated on step completion)
    for (;;) {
        __syncthreads();
        if (tid == 0) s_idx = (int)atomicAdd(&g_tile, 1u);
        __syncthreads();
        int idx = s_idx;
        if (idx >= NTILE_V) break;
        int m = idx / (VOCAB_ / 128);
        int n = idx - m * (VOCAB_ / 128);
        if (tid == 0) {
            const volatile unsigned* f = &g_scnt[2 * m + 1];
            while (*f < 32u) __nanosleep(256);
        }
        __syncthreads();
        __threadfence();
        gemm_tile64<true, true>(g_attn, Wproj, bproj, out, m * 64, n * 128, VOCAB_,
                                &su.gm);
    }
}

// ---------------- launch ----------------
extern "C" void kernel_launch(void* const* d_in, const int* in_sizes, int n_in, void* d_out,
                              int out_size) {
    (void)in_sizes;
    (void)n_in;
    (void)out_size;
    const float* enc = (const float*)d_in[0];
    const int* dec = (const int*)d_in[1];
    const float* h0 = (const float*)d_in[2];
    const float* noise = (const float*)d_in[3];
    const float* emb = (const float*)d_in[4];
    const float* W_ih = (const float*)d_in[5];
    const float* b_ih = (const float*)d_in[6];
    const float* W_hh = (const float*)d_in[7];
    const float* b_hh = (const float*)d_in[8];
    const float* Wm = (const float*)d_in[9];
    const float* Vm = (const float*)d_in[10];
    const float* bm = (const float*)d_in[11];
    const float* vvm = (const float*)d_in[12];
    const float* gm = (const float*)d_in[13];
    const float* vbm = (const float*)d_in[14];
    const float* rm = (const float*)d_in[15];
    const float* Wc = (const float*)d_in[16];
    const float* Vc = (const float*)d_in[17];
    const float* bc = (const float*)d_in[18];
    const float* vvc = (const float*)d_in[19];
    const float* gc = (const float*)d_in[20];
    const float* vbc = (const float*)d_in[21];
    const float* rc = (const float*)d_in[22];
    const float* W_comb = (const float*)d_in[23];
    const float* W_proj = (const float*)d_in[24];
    const float* b_proj = (const float*)d_in[25];
    float* out = (float*)d_out;

    k_init<<<97, 256>>>(W_ih, b_ih, W_hh, b_hh, W_comb, Wm, Wc, bm, bc, vvm, gm, vbm, rm,
                        vvc, gc, vbc, rc);
    k_xw<<<dim3(TDEC + 1, B_), 256>>>(dec, emb);
    k_phase1<<<296, 256>>>(enc, h0, Vm, Vc);
    k_energy<<<444, 256>>>(noise);
    k_post<<<296, 256>>>(enc, W_proj, b_proj, out);
}